// round 1
// baseline (speedup 1.0000x reference)
#include <cuda_runtime.h>

#define NTHREADS 256
#define PI_HALF 1.57079632679489662f

struct C2 { float r, i; };

__device__ __forceinline__ C2 cmul(C2 a, C2 b) {
    C2 o;
    o.r = fmaf(a.r, b.r, -a.i * b.i);
    o.i = fmaf(a.r, b.i,  a.i * b.r);
    return o;
}

__global__ void __launch_bounds__(NTHREADS)
qae_kernel(const float* __restrict__ x,
           const float* __restrict__ qw,
           const float* __restrict__ W1, const float* __restrict__ b1,
           const float* __restrict__ W2, const float* __restrict__ b2,
           const float* __restrict__ W3, const float* __restrict__ b3,
           float* __restrict__ out, int nrows)
{
    // ---- shared weights (float4-aligned for LDS.128) ----
    __shared__ __align__(16) float sW1[64];
    __shared__ __align__(16) float sW2[512];
    __shared__ __align__(16) float sW3[512];
    __shared__ __align__(16) float sb1[16];
    __shared__ __align__(16) float sb2[32];
    __shared__ __align__(16) float sb3[16];
    __shared__ float s_cq[4], s_sq[4], s_pc[4], s_ps[4];

    const int tid = threadIdx.x;
    for (int i = tid; i < 64;  i += NTHREADS) sW1[i] = W1[i];
    for (int i = tid; i < 512; i += NTHREADS) sW2[i] = W2[i];
    for (int i = tid; i < 512; i += NTHREADS) sW3[i] = W3[i];
    if (tid < 16) sb1[tid] = b1[tid];
    if (tid < 32) sb2[tid] = b2[tid];
    if (tid < 16) sb3[tid] = b3[tid];
    if (tid < 4) {
        float sy, cy, sz, cz;
        __sincosf(0.5f * qw[2 * tid],     &sy, &cy);
        __sincosf(0.5f * qw[2 * tid + 1], &sz, &cz);
        s_cq[tid] = cy; s_sq[tid] = sy;
        s_pc[tid] = cz; s_ps[tid] = sz;
    }
    __syncthreads();

    const int r = blockIdx.x * NTHREADS + tid;
    if (r >= nrows) return;

    // ---- load the 8 used features ----
    const float4* xp = reinterpret_cast<const float4*>(x + (size_t)r * 16);
    float4 xa = xp[0];
    float4 xb = xp[1];
    float xs[8] = {xa.x, xa.y, xa.z, xa.w, xb.x, xb.y, xb.z, xb.w};

    // ---- per-qubit state after RY(x[w]*pi), RZ(x[w+4]*pi) on |0> ----
    // u0 = (c*pc, -c*ps), u1 = (s*pc, s*ps)
    C2 u0[4], u1[4];
#pragma unroll
    for (int w = 0; w < 4; w++) {
        float s, c, ps, pc;
        __sincosf(xs[w]     * PI_HALF, &s,  &c);
        __sincosf(xs[w + 4] * PI_HALF, &ps, &pc);
        u0[w].r = c * pc;  u0[w].i = -c * ps;
        u1[w].r = s * pc;  u1[w].i =  s * ps;
    }

    // ---- product state: a[i], bit of wire w is (i>>(3-w))&1 ----
    C2 t01[4], t23[4], a[16];
    t01[0] = cmul(u0[0], u0[1]); t01[1] = cmul(u0[0], u1[1]);
    t01[2] = cmul(u1[0], u0[1]); t01[3] = cmul(u1[0], u1[1]);
    t23[0] = cmul(u0[2], u0[3]); t23[1] = cmul(u0[2], u1[3]);
    t23[2] = cmul(u1[2], u0[3]); t23[3] = cmul(u1[2], u1[3]);
#pragma unroll
    for (int hi = 0; hi < 4; hi++)
#pragma unroll
        for (int lo = 0; lo < 4; lo++)
            a[hi * 4 + lo] = cmul(t01[hi], t23[lo]);

    // ---- CNOT chain (compile-time swaps) ----
#define SWAP_AMP(p, q) { C2 tmp = a[p]; a[p] = a[q]; a[q] = tmp; }
#define CNOT_CHAIN()                                              \
    SWAP_AMP(8, 12)  SWAP_AMP(9, 13)  SWAP_AMP(10, 14) SWAP_AMP(11, 15) \
    SWAP_AMP(4, 6)   SWAP_AMP(5, 7)   SWAP_AMP(12, 14) SWAP_AMP(13, 15) \
    SWAP_AMP(2, 3)   SWAP_AMP(6, 7)   SWAP_AMP(10, 11) SWAP_AMP(14, 15)

    CNOT_CHAIN();

    // ---- trainable layer: fused RZ(qw1)*RY(qw0) per wire ----
#pragma unroll
    for (int w = 0; w < 4; w++) {
        const int m = 8 >> w;
        const float cq = s_cq[w], sq = s_sq[w];
        const float pc = s_pc[w], ps = s_ps[w];
#pragma unroll
        for (int i = 0; i < 16; i++) {
            if (i & m) continue;
            C2 A = a[i], B = a[i | m];
            C2 t0, t1;
            t0.r = fmaf(cq, A.r, -sq * B.r);
            t0.i = fmaf(cq, A.i, -sq * B.i);
            t1.r = fmaf(sq, A.r,  cq * B.r);
            t1.i = fmaf(sq, A.i,  cq * B.i);
            // t0 * (pc - i ps) ; t1 * (pc + i ps)
            a[i].r     = fmaf(t0.r, pc,  t0.i * ps);
            a[i].i     = fmaf(t0.i, pc, -t0.r * ps);
            a[i | m].r = fmaf(t1.r, pc, -t1.i * ps);
            a[i | m].i = fmaf(t1.i, pc,  t1.r * ps);
        }
    }

    CNOT_CHAIN();

    // ---- probabilities and PauliZ expectations ----
    float p[16];
#pragma unroll
    for (int i = 0; i < 16; i++)
        p[i] = fmaf(a[i].r, a[i].r, a[i].i * a[i].i);

    float zv[4];
#pragma unroll
    for (int w = 0; w < 4; w++) {
        const int m = 8 >> w;
        float acc = 0.f;
#pragma unroll
        for (int i = 0; i < 16; i++)
            acc += (i & m) ? -p[i] : p[i];
        zv[w] = acc;
    }

    // ---- MLP: 4 -> 16 (relu) -> 32 (relu) -> 16 ----
    float h1[16];
#pragma unroll
    for (int j = 0; j < 16; j++) {
        float4 wr = reinterpret_cast<const float4*>(sW1)[j];
        float acc = sb1[j];
        acc = fmaf(wr.x, zv[0], acc);
        acc = fmaf(wr.y, zv[1], acc);
        acc = fmaf(wr.z, zv[2], acc);
        acc = fmaf(wr.w, zv[3], acc);
        h1[j] = fmaxf(acc, 0.f);
    }

    float h2[32];
#pragma unroll
    for (int j = 0; j < 32; j++) {
        const float4* wr = reinterpret_cast<const float4*>(sW2 + j * 16);
        float acc = sb2[j];
#pragma unroll
        for (int k4 = 0; k4 < 4; k4++) {
            float4 w4 = wr[k4];
            acc = fmaf(w4.x, h1[k4 * 4 + 0], acc);
            acc = fmaf(w4.y, h1[k4 * 4 + 1], acc);
            acc = fmaf(w4.z, h1[k4 * 4 + 2], acc);
            acc = fmaf(w4.w, h1[k4 * 4 + 3], acc);
        }
        h2[j] = fmaxf(acc, 0.f);
    }

    float4* op = reinterpret_cast<float4*>(out + (size_t)r * 16);
    float o[16];
#pragma unroll
    for (int j = 0; j < 16; j++) {
        const float4* wr = reinterpret_cast<const float4*>(sW3 + j * 32);
        float acc = sb3[j];
#pragma unroll
        for (int k4 = 0; k4 < 8; k4++) {
            float4 w4 = wr[k4];
            acc = fmaf(w4.x, h2[k4 * 4 + 0], acc);
            acc = fmaf(w4.y, h2[k4 * 4 + 1], acc);
            acc = fmaf(w4.z, h2[k4 * 4 + 2], acc);
            acc = fmaf(w4.w, h2[k4 * 4 + 3], acc);
        }
        o[j] = acc;
    }
#pragma unroll
    for (int q = 0; q < 4; q++)
        op[q] = make_float4(o[q * 4], o[q * 4 + 1], o[q * 4 + 2], o[q * 4 + 3]);
}

extern "C" void kernel_launch(void* const* d_in, const int* in_sizes, int n_in,
                              void* d_out, int out_size) {
    const float* x  = (const float*)d_in[0];
    const float* qw = (const float*)d_in[1];
    const float* W1 = (const float*)d_in[2];
    const float* b1 = (const float*)d_in[3];
    const float* W2 = (const float*)d_in[4];
    const float* b2 = (const float*)d_in[5];
    const float* W3 = (const float*)d_in[6];
    const float* b3 = (const float*)d_in[7];
    float* out = (float*)d_out;

    int nrows = in_sizes[0] / 16;
    int grid = (nrows + NTHREADS - 1) / NTHREADS;
    qae_kernel<<<grid, NTHREADS>>>(x, qw, W1, b1, W2, b2, W3, b3, out, nrows);
}

// round 2
// speedup vs baseline: 1.1647x; 1.1647x over previous
#include <cuda_runtime.h>

#define NT 128
#define PI_HALF 1.57079632679489662f

// ---------- packed f32x2 primitives ----------
struct P2 { union { float2 f; unsigned long long u; }; };

__device__ __forceinline__ P2 mk2(float a, float b) { P2 p; p.f.x = a; p.f.y = b; return p; }
__device__ __forceinline__ P2 dup2(float a) { return mk2(a, a); }

__device__ __forceinline__ P2 fma2(P2 a, P2 b, P2 c) {
    P2 d;
    asm("fma.rn.f32x2 %0, %1, %2, %3;" : "=l"(d.u) : "l"(a.u), "l"(b.u), "l"(c.u));
    return d;
}
__device__ __forceinline__ P2 mul2(P2 a, P2 b) {
    P2 d;
    asm("mul.rn.f32x2 %0, %1, %2;" : "=l"(d.u) : "l"(a.u), "l"(b.u));
    return d;
}
__device__ __forceinline__ P2 add2(P2 a, P2 b) {
    P2 d;
    asm("add.rn.f32x2 %0, %1, %2;" : "=l"(d.u) : "l"(a.u), "l"(b.u));
    return d;
}
__device__ __forceinline__ P2 neg2(P2 a) { P2 d; d.u = a.u ^ 0x8000000080000000ULL; return d; }
__device__ __forceinline__ P2 sub2(P2 a, P2 b) { return add2(a, neg2(b)); }
__device__ __forceinline__ P2 relu2(P2 a) { P2 d; d.f.x = fmaxf(a.f.x, 0.f); d.f.y = fmaxf(a.f.y, 0.f); return d; }

struct CP { P2 r, i; };
__device__ __forceinline__ CP cmulp(CP a, CP b) {
    CP o;
    o.r = fma2(a.r, b.r, neg2(mul2(a.i, b.i)));
    o.i = fma2(a.r, b.i, mul2(a.i, b.r));
    return o;
}

__global__ void __launch_bounds__(NT)
qae2_kernel(const float* __restrict__ x,
            const float* __restrict__ qw,
            const float* __restrict__ W1, const float* __restrict__ b1,
            const float* __restrict__ W2, const float* __restrict__ b2,
            const float* __restrict__ W3, const float* __restrict__ b3,
            float* __restrict__ out, int nrows)
{
    // weights stored duplicated: float2 (w,w) so LDS.128 yields 2 packed operands
    __shared__ __align__(16) float2 sW1[64];
    __shared__ __align__(16) float2 sW2[512];
    __shared__ __align__(16) float2 sW3[512];
    __shared__ __align__(16) float2 sb1[16];
    __shared__ __align__(16) float2 sb2[32];
    __shared__ __align__(16) float2 sb3[16];
    __shared__ float sgq[16];  // [cq x4][sq x4][pc x4][ps x4]

    const int tid = threadIdx.x;
    for (int i = tid; i < 64; i += NT) { float w = W1[i]; sW1[i] = make_float2(w, w); }
    for (int i = tid; i < 512; i += NT) {
        float w2 = W2[i]; sW2[i] = make_float2(w2, w2);
        float w3 = W3[i]; sW3[i] = make_float2(w3, w3);
    }
    if (tid < 16) { float v = b1[tid]; sb1[tid] = make_float2(v, v); }
    if (tid < 32) { float v = b2[tid]; sb2[tid] = make_float2(v, v); }
    if (tid < 16) { float v = b3[tid]; sb3[tid] = make_float2(v, v); }
    if (tid < 4) {
        float sy, cy, sz, cz;
        __sincosf(0.5f * qw[2 * tid],     &sy, &cy);
        __sincosf(0.5f * qw[2 * tid + 1], &sz, &cz);
        sgq[tid] = cy; sgq[4 + tid] = sy; sgq[8 + tid] = cz; sgq[12 + tid] = sz;
    }
    __syncthreads();

    const int r0 = blockIdx.x * (NT * 2) + tid;
    const int r1 = r0 + NT;
    if (r0 >= nrows) return;
    const bool has1 = (r1 < nrows);

    // ---- load the 8 used features for both rows ----
    const float4* xp0 = reinterpret_cast<const float4*>(x + (size_t)r0 * 16);
    const float4* xp1 = reinterpret_cast<const float4*>(x + (size_t)(has1 ? r1 : r0) * 16);
    float4 a0 = xp0[0], a1 = xp0[1];
    float4 c0 = xp1[0], c1 = xp1[1];
    float xsA[8] = {a0.x, a0.y, a0.z, a0.w, a1.x, a1.y, a1.z, a1.w};
    float xsB[8] = {c0.x, c0.y, c0.z, c0.w, c1.x, c1.y, c1.z, c1.w};

    // ---- per-qubit single-qubit states after RY(x*pi), RZ(x'*pi) on |0> ----
    CP u0[4], u1[4];
#pragma unroll
    for (int w = 0; w < 4; w++) {
        float sA, cA, psA, pcA, sB, cB, psB, pcB;
        __sincosf(xsA[w]     * PI_HALF, &sA,  &cA);
        __sincosf(xsA[w + 4] * PI_HALF, &psA, &pcA);
        __sincosf(xsB[w]     * PI_HALF, &sB,  &cB);
        __sincosf(xsB[w + 4] * PI_HALF, &psB, &pcB);
        P2 c = mk2(cA, cB), s = mk2(sA, sB);
        P2 pc = mk2(pcA, pcB), ps = mk2(psA, psB);
        u0[w].r = mul2(c, pc);  u0[w].i = neg2(mul2(c, ps));
        u1[w].r = mul2(s, pc);  u1[w].i = mul2(s, ps);
    }

    // ---- product state: amp index i, wire w bit = (i >> (3-w)) & 1 ----
    CP t01[4], t23[4], a[16];
    t01[0] = cmulp(u0[0], u0[1]); t01[1] = cmulp(u0[0], u1[1]);
    t01[2] = cmulp(u1[0], u0[1]); t01[3] = cmulp(u1[0], u1[1]);
    t23[0] = cmulp(u0[2], u0[3]); t23[1] = cmulp(u0[2], u1[3]);
    t23[2] = cmulp(u1[2], u0[3]); t23[3] = cmulp(u1[2], u1[3]);
#pragma unroll
    for (int hi = 0; hi < 4; hi++)
#pragma unroll
        for (int lo = 0; lo < 4; lo++)
            a[hi * 4 + lo] = cmulp(t01[hi], t23[lo]);

#define SWAP_AMP(p, q) { CP tmp = a[p]; a[p] = a[q]; a[q] = tmp; }
#define CNOT_CHAIN()                                                    \
    SWAP_AMP(8, 12)  SWAP_AMP(9, 13)  SWAP_AMP(10, 14) SWAP_AMP(11, 15) \
    SWAP_AMP(4, 6)   SWAP_AMP(5, 7)   SWAP_AMP(12, 14) SWAP_AMP(13, 15) \
    SWAP_AMP(2, 3)   SWAP_AMP(6, 7)   SWAP_AMP(10, 11) SWAP_AMP(14, 15)

    CNOT_CHAIN();

    // ---- trainable layer: fused RZ(qw1)*RY(qw0) per wire (uniform angles) ----
#pragma unroll
    for (int w = 0; w < 4; w++) {
        const int m = 8 >> w;
        P2 cq  = dup2(sgq[w]);
        P2 sq  = dup2(sgq[4 + w]);
        P2 nsq = neg2(sq);
        P2 pc  = dup2(sgq[8 + w]);
        P2 ps  = dup2(sgq[12 + w]);
        P2 nps = neg2(ps);
#pragma unroll
        for (int i = 0; i < 16; i++) {
            if (i & m) continue;
            CP A = a[i], B = a[i | m];
            P2 t0r = fma2(cq, A.r, mul2(nsq, B.r));
            P2 t0i = fma2(cq, A.i, mul2(nsq, B.i));
            P2 t1r = fma2(sq, A.r, mul2(cq, B.r));
            P2 t1i = fma2(sq, A.i, mul2(cq, B.i));
            a[i].r     = fma2(t0r, pc, mul2(t0i, ps));
            a[i].i     = fma2(t0i, pc, mul2(t0r, nps));
            a[i | m].r = fma2(t1r, pc, mul2(t1i, nps));
            a[i | m].i = fma2(t1i, pc, mul2(t1r, ps));
        }
    }

    CNOT_CHAIN();

    // ---- probabilities ----
    P2 p[16];
#pragma unroll
    for (int i = 0; i < 16; i++)
        p[i] = fma2(a[i].r, a[i].r, mul2(a[i].i, a[i].i));

    // ---- PauliZ expectations via shared sum tree ----
    P2 dd[8], ee[8];
#pragma unroll
    for (int k = 0; k < 8; k++) {
        dd[k] = sub2(p[2 * k], p[2 * k + 1]);
        ee[k] = add2(p[2 * k], p[2 * k + 1]);
    }
    P2 z3 = add2(add2(add2(dd[0], dd[1]), add2(dd[2], dd[3])),
                 add2(add2(dd[4], dd[5]), add2(dd[6], dd[7])));
    P2 ff[4], gg[4];
#pragma unroll
    for (int k = 0; k < 4; k++) {
        ff[k] = sub2(ee[2 * k], ee[2 * k + 1]);
        gg[k] = add2(ee[2 * k], ee[2 * k + 1]);
    }
    P2 z2 = add2(add2(ff[0], ff[1]), add2(ff[2], ff[3]));
    P2 z1 = add2(sub2(gg[0], gg[1]), sub2(gg[2], gg[3]));
    P2 z0 = sub2(add2(gg[0], gg[1]), add2(gg[2], gg[3]));
    P2 zv[4] = {z0, z1, z2, z3};   // wire w <-> mask 8>>w

    // ---- MLP: 4 -> 16 (relu) -> 32 (relu) -> 16, packed ----
    P2 h1[16];
#pragma unroll
    for (int j = 0; j < 16; j++) {
        const float4* wp = reinterpret_cast<const float4*>(sW1 + j * 4);
        float4 wa = wp[0], wb = wp[1];
        P2 acc; acc.f = sb1[j];
        acc = fma2(mk2(wa.x, wa.y), zv[0], acc);
        acc = fma2(mk2(wa.z, wa.w), zv[1], acc);
        acc = fma2(mk2(wb.x, wb.y), zv[2], acc);
        acc = fma2(mk2(wb.z, wb.w), zv[3], acc);
        h1[j] = relu2(acc);
    }

    P2 h2[32];
#pragma unroll
    for (int j = 0; j < 32; j++) {
        const float4* wp = reinterpret_cast<const float4*>(sW2 + j * 16);
        P2 acc; acc.f = sb2[j];
#pragma unroll
        for (int k = 0; k < 8; k++) {
            float4 w4 = wp[k];
            acc = fma2(mk2(w4.x, w4.y), h1[2 * k],     acc);
            acc = fma2(mk2(w4.z, w4.w), h1[2 * k + 1], acc);
        }
        h2[j] = relu2(acc);
    }

    float4* op0 = reinterpret_cast<float4*>(out + (size_t)r0 * 16);
    float4* op1 = reinterpret_cast<float4*>(out + (size_t)r1 * 16);
#pragma unroll
    for (int q = 0; q < 4; q++) {
        P2 o[4];
#pragma unroll
        for (int jj = 0; jj < 4; jj++) {
            int j = q * 4 + jj;
            const float4* wp = reinterpret_cast<const float4*>(sW3 + j * 32);
            P2 acc; acc.f = sb3[j];
#pragma unroll
            for (int k = 0; k < 16; k++) {
                float4 w4 = wp[k];
                acc = fma2(mk2(w4.x, w4.y), h2[2 * k],     acc);
                acc = fma2(mk2(w4.z, w4.w), h2[2 * k + 1], acc);
            }
            o[jj] = acc;
        }
        op0[q] = make_float4(o[0].f.x, o[1].f.x, o[2].f.x, o[3].f.x);
        if (has1)
            op1[q] = make_float4(o[0].f.y, o[1].f.y, o[2].f.y, o[3].f.y);
    }
}

extern "C" void kernel_launch(void* const* d_in, const int* in_sizes, int n_in,
                              void* d_out, int out_size) {
    const float* x  = (const float*)d_in[0];
    const float* qw = (const float*)d_in[1];
    const float* W1 = (const float*)d_in[2];
    const float* b1 = (const float*)d_in[3];
    const float* W2 = (const float*)d_in[4];
    const float* b2 = (const float*)d_in[5];
    const float* W3 = (const float*)d_in[6];
    const float* b3 = (const float*)d_in[7];
    float* out = (float*)d_out;

    int nrows = in_sizes[0] / 16;
    int grid = (nrows + NT * 2 - 1) / (NT * 2);
    qae2_kernel<<<grid, NT>>>(x, qw, W1, b1, W2, b2, W3, b3, out, nrows);
}

// round 3
// speedup vs baseline: 1.6234x; 1.3939x over previous
#include <cuda_runtime.h>

#define NT 128
#define PI_HALF 1.57079632679489662f

// ---------- packed f32x2 primitives ----------
struct P2 { union { float2 f; unsigned long long u; }; };

__device__ __forceinline__ P2 mk2(float a, float b) { P2 p; p.f.x = a; p.f.y = b; return p; }
__device__ __forceinline__ P2 dup2(float a) { return mk2(a, a); }

__device__ __forceinline__ P2 fma2(P2 a, P2 b, P2 c) {
    P2 d;
    asm("fma.rn.f32x2 %0, %1, %2, %3;" : "=l"(d.u) : "l"(a.u), "l"(b.u), "l"(c.u));
    return d;
}
__device__ __forceinline__ P2 mul2(P2 a, P2 b) {
    P2 d;
    asm("mul.rn.f32x2 %0, %1, %2;" : "=l"(d.u) : "l"(a.u), "l"(b.u));
    return d;
}
__device__ __forceinline__ P2 add2(P2 a, P2 b) {
    P2 d;
    asm("add.rn.f32x2 %0, %1, %2;" : "=l"(d.u) : "l"(a.u), "l"(b.u));
    return d;
}
__device__ __forceinline__ P2 neg2(P2 a) { P2 d; d.u = a.u ^ 0x8000000080000000ULL; return d; }
__device__ __forceinline__ P2 sub2(P2 a, P2 b) { return add2(a, neg2(b)); }
__device__ __forceinline__ P2 relu2(P2 a) { P2 d; d.f.x = fmaxf(a.f.x, 0.f); d.f.y = fmaxf(a.f.y, 0.f); return d; }

struct CP { P2 r, i; };
__device__ __forceinline__ CP cmulp(CP a, CP b) {
    CP o;
    o.r = fma2(a.r, b.r, neg2(mul2(a.i, b.i)));
    o.i = fma2(a.r, b.i, mul2(a.i, b.r));
    return o;
}

__global__ void __launch_bounds__(NT)
qae3_kernel(const float* __restrict__ x,
            const float* __restrict__ qw,
            const float* __restrict__ W1, const float* __restrict__ b1,
            const float* __restrict__ W2, const float* __restrict__ b2,
            const float* __restrict__ W3, const float* __restrict__ b3,
            float* __restrict__ out, int nrows)
{
    // Neuron-pair interleaved weights: sW[p*K + k] = (W[2p][k], W[2p+1][k]).
    // Each weight stored ONCE; one float2 is a ready f32x2 operand for 2 neurons,
    // reused for both rows handled by the thread.
    __shared__ __align__(16) float2 sW1[32];    // 8 pairs x 4
    __shared__ __align__(16) float2 sW2[256];   // 16 pairs x 16
    __shared__ __align__(16) float2 sW3[256];   // 8 pairs x 32
    __shared__ __align__(16) float2 sb1[8];
    __shared__ __align__(16) float2 sb2[16];
    __shared__ __align__(16) float2 sb3[8];
    __shared__ float sgq[16];  // [cq x4][sq x4][pc x4][ps x4]

    const int tid = threadIdx.x;
    for (int i = tid; i < 32; i += NT) {
        int p = i >> 2, k = i & 3;
        sW1[i] = make_float2(W1[(2 * p) * 4 + k], W1[(2 * p + 1) * 4 + k]);
    }
    for (int i = tid; i < 256; i += NT) {
        int p2 = i >> 4, k2 = i & 15;
        sW2[i] = make_float2(W2[(2 * p2) * 16 + k2], W2[(2 * p2 + 1) * 16 + k2]);
        int p3 = i >> 5, k3 = i & 31;
        sW3[i] = make_float2(W3[(2 * p3) * 32 + k3], W3[(2 * p3 + 1) * 32 + k3]);
    }
    if (tid < 8)  sb1[tid] = make_float2(b1[2 * tid], b1[2 * tid + 1]);
    if (tid < 16) sb2[tid] = make_float2(b2[2 * tid], b2[2 * tid + 1]);
    if (tid < 8)  sb3[tid] = make_float2(b3[2 * tid], b3[2 * tid + 1]);
    if (tid < 4) {
        float sy, cy, sz, cz;
        __sincosf(0.5f * qw[2 * tid],     &sy, &cy);
        __sincosf(0.5f * qw[2 * tid + 1], &sz, &cz);
        sgq[tid] = cy; sgq[4 + tid] = sy; sgq[8 + tid] = cz; sgq[12 + tid] = sz;
    }
    __syncthreads();

    const int r0 = blockIdx.x * (NT * 2) + tid;
    const int r1 = r0 + NT;
    if (r0 >= nrows) return;
    const bool has1 = (r1 < nrows);

    // ---- load the 8 used features for both rows ----
    const float4* xp0 = reinterpret_cast<const float4*>(x + (size_t)r0 * 16);
    const float4* xp1 = reinterpret_cast<const float4*>(x + (size_t)(has1 ? r1 : r0) * 16);
    float4 a0 = xp0[0], a1 = xp0[1];
    float4 c0 = xp1[0], c1 = xp1[1];
    float xsA[8] = {a0.x, a0.y, a0.z, a0.w, a1.x, a1.y, a1.z, a1.w};
    float xsB[8] = {c0.x, c0.y, c0.z, c0.w, c1.x, c1.y, c1.z, c1.w};

    // ---- per-qubit single-qubit states after RY(x*pi), RZ(x'*pi) on |0>, rows packed ----
    CP u0[4], u1[4];
#pragma unroll
    for (int w = 0; w < 4; w++) {
        float sA, cA, psA, pcA, sB, cB, psB, pcB;
        __sincosf(xsA[w]     * PI_HALF, &sA,  &cA);
        __sincosf(xsA[w + 4] * PI_HALF, &psA, &pcA);
        __sincosf(xsB[w]     * PI_HALF, &sB,  &cB);
        __sincosf(xsB[w + 4] * PI_HALF, &psB, &pcB);
        P2 c = mk2(cA, cB), s = mk2(sA, sB);
        P2 pc = mk2(pcA, pcB), ps = mk2(psA, psB);
        u0[w].r = mul2(c, pc);  u0[w].i = neg2(mul2(c, ps));
        u1[w].r = mul2(s, pc);  u1[w].i = mul2(s, ps);
    }

    // ---- product state: amp index i, wire w bit = (i >> (3-w)) & 1 ----
    CP t01[4], t23[4], a[16];
    t01[0] = cmulp(u0[0], u0[1]); t01[1] = cmulp(u0[0], u1[1]);
    t01[2] = cmulp(u1[0], u0[1]); t01[3] = cmulp(u1[0], u1[1]);
    t23[0] = cmulp(u0[2], u0[3]); t23[1] = cmulp(u0[2], u1[3]);
    t23[2] = cmulp(u1[2], u0[3]); t23[3] = cmulp(u1[2], u1[3]);
#pragma unroll
    for (int hi = 0; hi < 4; hi++)
#pragma unroll
        for (int lo = 0; lo < 4; lo++)
            a[hi * 4 + lo] = cmulp(t01[hi], t23[lo]);

#define SWAP_AMP(p, q) { CP tmp = a[p]; a[p] = a[q]; a[q] = tmp; }
#define CNOT_CHAIN()                                                    \
    SWAP_AMP(8, 12)  SWAP_AMP(9, 13)  SWAP_AMP(10, 14) SWAP_AMP(11, 15) \
    SWAP_AMP(4, 6)   SWAP_AMP(5, 7)   SWAP_AMP(12, 14) SWAP_AMP(13, 15) \
    SWAP_AMP(2, 3)   SWAP_AMP(6, 7)   SWAP_AMP(10, 11) SWAP_AMP(14, 15)

    CNOT_CHAIN();

    // ---- trainable layer: fused RZ(qw1)*RY(qw0) per wire (uniform angles) ----
#pragma unroll
    for (int w = 0; w < 4; w++) {
        const int m = 8 >> w;
        P2 cq  = dup2(sgq[w]);
        P2 sq  = dup2(sgq[4 + w]);
        P2 nsq = neg2(sq);
        P2 pc  = dup2(sgq[8 + w]);
        P2 ps  = dup2(sgq[12 + w]);
        P2 nps = neg2(ps);
#pragma unroll
        for (int i = 0; i < 16; i++) {
            if (i & m) continue;
            CP A = a[i], B = a[i | m];
            P2 t0r = fma2(cq, A.r, mul2(nsq, B.r));
            P2 t0i = fma2(cq, A.i, mul2(nsq, B.i));
            P2 t1r = fma2(sq, A.r, mul2(cq, B.r));
            P2 t1i = fma2(sq, A.i, mul2(cq, B.i));
            a[i].r     = fma2(t0r, pc, mul2(t0i, ps));
            a[i].i     = fma2(t0i, pc, mul2(t0r, nps));
            a[i | m].r = fma2(t1r, pc, mul2(t1i, nps));
            a[i | m].i = fma2(t1i, pc, mul2(t1r, ps));
        }
    }

    CNOT_CHAIN();

    // ---- probabilities ----
    P2 p[16];
#pragma unroll
    for (int i = 0; i < 16; i++)
        p[i] = fma2(a[i].r, a[i].r, mul2(a[i].i, a[i].i));

    // ---- PauliZ expectations (rows still packed in lanes) ----
    P2 dd[8], ee[8];
#pragma unroll
    for (int k = 0; k < 8; k++) {
        dd[k] = sub2(p[2 * k], p[2 * k + 1]);
        ee[k] = add2(p[2 * k], p[2 * k + 1]);
    }
    P2 z3 = add2(add2(add2(dd[0], dd[1]), add2(dd[2], dd[3])),
                 add2(add2(dd[4], dd[5]), add2(dd[6], dd[7])));
    P2 ff[4], gg[4];
#pragma unroll
    for (int k = 0; k < 4; k++) {
        ff[k] = sub2(ee[2 * k], ee[2 * k + 1]);
        gg[k] = add2(ee[2 * k], ee[2 * k + 1]);
    }
    P2 z2 = add2(add2(ff[0], ff[1]), add2(ff[2], ff[3]));
    P2 z1 = add2(sub2(gg[0], gg[1]), sub2(gg[2], gg[3]));
    P2 z0 = sub2(add2(gg[0], gg[1]), add2(gg[2], gg[3]));
    P2 zv[4] = {z0, z1, z2, z3};   // wire w <-> mask 8>>w ; lanes = (rowA, rowB)

    // ================= MLP: neuron-pair packed, weights shared across rows ==========
    // Layer 1: 4 -> 16 ; 8 neuron pairs per row
    P2 zdA[4], zdB[4];
#pragma unroll
    for (int k = 0; k < 4; k++) { zdA[k] = dup2(zv[k].f.x); zdB[k] = dup2(zv[k].f.y); }

    P2 h1pA[8], h1pB[8];
#pragma unroll
    for (int pp = 0; pp < 8; pp++) {
        const float4* wp = reinterpret_cast<const float4*>(sW1 + pp * 4);
        float4 w0 = wp[0], w1 = wp[1];
        P2 wk0 = mk2(w0.x, w0.y), wk1 = mk2(w0.z, w0.w);
        P2 wk2 = mk2(w1.x, w1.y), wk3 = mk2(w1.z, w1.w);
        P2 accA; accA.f = sb1[pp];
        P2 accB = accA;
        accA = fma2(wk0, zdA[0], accA); accB = fma2(wk0, zdB[0], accB);
        accA = fma2(wk1, zdA[1], accA); accB = fma2(wk1, zdB[1], accB);
        accA = fma2(wk2, zdA[2], accA); accB = fma2(wk2, zdB[2], accB);
        accA = fma2(wk3, zdA[3], accA); accB = fma2(wk3, zdB[3], accB);
        h1pA[pp] = relu2(accA); h1pB[pp] = relu2(accB);
    }

    // Layer 2: 16 -> 32 ; 16 neuron pairs per row, k chunked by 8
    P2 accA2[16], accB2[16];
#pragma unroll
    for (int pp = 0; pp < 16; pp++) { accA2[pp].f = sb2[pp]; accB2[pp] = accA2[pp]; }
#pragma unroll
    for (int ch = 0; ch < 2; ch++) {
        P2 hdA[8], hdB[8];
#pragma unroll
        for (int kk = 0; kk < 8; kk++) {
            int k = ch * 8 + kk;
            float vA = (k & 1) ? h1pA[k >> 1].f.y : h1pA[k >> 1].f.x;
            float vB = (k & 1) ? h1pB[k >> 1].f.y : h1pB[k >> 1].f.x;
            hdA[kk] = dup2(vA); hdB[kk] = dup2(vB);
        }
#pragma unroll
        for (int pp = 0; pp < 16; pp++) {
            const float4* wp = reinterpret_cast<const float4*>(sW2 + pp * 16 + ch * 8);
#pragma unroll
            for (int k4 = 0; k4 < 4; k4++) {
                float4 w = wp[k4];
                P2 wa = mk2(w.x, w.y), wb = mk2(w.z, w.w);
                accA2[pp] = fma2(wa, hdA[2 * k4],     accA2[pp]);
                accB2[pp] = fma2(wa, hdB[2 * k4],     accB2[pp]);
                accA2[pp] = fma2(wb, hdA[2 * k4 + 1], accA2[pp]);
                accB2[pp] = fma2(wb, hdB[2 * k4 + 1], accB2[pp]);
            }
        }
    }
#pragma unroll
    for (int pp = 0; pp < 16; pp++) { accA2[pp] = relu2(accA2[pp]); accB2[pp] = relu2(accB2[pp]); }

    // Layer 3: 32 -> 16 ; 8 neuron pairs per row, k chunked by 8
    P2 oA[8], oB[8];
#pragma unroll
    for (int pp = 0; pp < 8; pp++) { oA[pp].f = sb3[pp]; oB[pp] = oA[pp]; }
#pragma unroll
    for (int ch = 0; ch < 4; ch++) {
        P2 hdA[8], hdB[8];
#pragma unroll
        for (int kk = 0; kk < 8; kk++) {
            int k = ch * 8 + kk;
            float vA = (k & 1) ? accA2[k >> 1].f.y : accA2[k >> 1].f.x;
            float vB = (k & 1) ? accB2[k >> 1].f.y : accB2[k >> 1].f.x;
            hdA[kk] = dup2(vA); hdB[kk] = dup2(vB);
        }
#pragma unroll
        for (int pp = 0; pp < 8; pp++) {
            const float4* wp = reinterpret_cast<const float4*>(sW3 + pp * 32 + ch * 8);
#pragma unroll
            for (int k4 = 0; k4 < 4; k4++) {
                float4 w = wp[k4];
                P2 wa = mk2(w.x, w.y), wb = mk2(w.z, w.w);
                oA[pp] = fma2(wa, hdA[2 * k4],     oA[pp]);
                oB[pp] = fma2(wa, hdB[2 * k4],     oB[pp]);
                oA[pp] = fma2(wb, hdA[2 * k4 + 1], oA[pp]);
                oB[pp] = fma2(wb, hdB[2 * k4 + 1], oB[pp]);
            }
        }
    }

    // ---- stores: oX[p] = (neuron 2p, neuron 2p+1) ----
    float4* op0 = reinterpret_cast<float4*>(out + (size_t)r0 * 16);
#pragma unroll
    for (int q = 0; q < 4; q++)
        op0[q] = make_float4(oA[2 * q].f.x, oA[2 * q].f.y, oA[2 * q + 1].f.x, oA[2 * q + 1].f.y);
    if (has1) {
        float4* op1 = reinterpret_cast<float4*>(out + (size_t)r1 * 16);
#pragma unroll
        for (int q = 0; q < 4; q++)
            op1[q] = make_float4(oB[2 * q].f.x, oB[2 * q].f.y, oB[2 * q + 1].f.x, oB[2 * q + 1].f.y);
    }
}

extern "C" void kernel_launch(void* const* d_in, const int* in_sizes, int n_in,
                              void* d_out, int out_size) {
    const float* x  = (const float*)d_in[0];
    const float* qw = (const float*)d_in[1];
    const float* W1 = (const float*)d_in[2];
    const float* b1 = (const float*)d_in[3];
    const float* W2 = (const float*)d_in[4];
    const float* b2 = (const float*)d_in[5];
    const float* W3 = (const float*)d_in[6];
    const float* b3 = (const float*)d_in[7];
    float* out = (float*)d_out;

    int nrows = in_sizes[0] / 16;
    int grid = (nrows + NT * 2 - 1) / (NT * 2);
    qae3_kernel<<<grid, NT>>>(x, qw, W1, b1, W2, b2, W3, b3, out, nrows);
}

// round 4
// speedup vs baseline: 1.8935x; 1.1664x over previous
#include <cuda_runtime.h>

#define NT 128
#define PI_F 3.14159265358979323846f

// ---------- packed f32x2 primitives ----------
struct P2 { union { float2 f; unsigned long long u; }; };

__device__ __forceinline__ P2 mk2(float a, float b) { P2 p; p.f.x = a; p.f.y = b; return p; }
__device__ __forceinline__ P2 dup2(float a) { return mk2(a, a); }

__device__ __forceinline__ P2 fma2(P2 a, P2 b, P2 c) {
    P2 d;
    asm("fma.rn.f32x2 %0, %1, %2, %3;" : "=l"(d.u) : "l"(a.u), "l"(b.u), "l"(c.u));
    return d;
}
__device__ __forceinline__ P2 mul2(P2 a, P2 b) {
    P2 d;
    asm("mul.rn.f32x2 %0, %1, %2;" : "=l"(d.u) : "l"(a.u), "l"(b.u));
    return d;
}
__device__ __forceinline__ P2 relu2(P2 a) { P2 d; d.f.x = fmaxf(a.f.x, 0.f); d.f.y = fmaxf(a.f.y, 0.f); return d; }

__global__ void __launch_bounds__(NT)
qae4_kernel(const float* __restrict__ x,
            const float* __restrict__ qw,
            const float* __restrict__ W1, const float* __restrict__ b1,
            const float* __restrict__ W2, const float* __restrict__ b2,
            const float* __restrict__ W3, const float* __restrict__ b3,
            float* __restrict__ out, int nrows)
{
    // Neuron-pair interleaved weights: sW[p*K + k] = (W[2p][k], W[2p+1][k]).
    __shared__ __align__(16) float2 sW1[32];
    __shared__ __align__(16) float2 sW2[256];
    __shared__ __align__(16) float2 sW3[256];
    __shared__ __align__(16) float2 sb1[8];
    __shared__ __align__(16) float2 sb2[16];
    __shared__ __align__(16) float2 sb3[8];
    __shared__ __align__(8)  float2 sK[30];   // Pauli-term coefficients, duplicated

    const int tid = threadIdx.x;
    for (int i = tid; i < 32; i += NT) {
        int p = i >> 2, k = i & 3;
        sW1[i] = make_float2(W1[(2 * p) * 4 + k], W1[(2 * p + 1) * 4 + k]);
    }
    for (int i = tid; i < 256; i += NT) {
        int p2 = i >> 4, k2 = i & 15;
        sW2[i] = make_float2(W2[(2 * p2) * 16 + k2], W2[(2 * p2 + 1) * 16 + k2]);
        int p3 = i >> 5, k3 = i & 31;
        sW3[i] = make_float2(W3[(2 * p3) * 32 + k3], W3[(2 * p3 + 1) * 32 + k3]);
    }
    if (tid < 8)  sb1[tid] = make_float2(b1[2 * tid], b1[2 * tid + 1]);
    if (tid < 16) sb2[tid] = make_float2(b2[2 * tid], b2[2 * tid + 1]);
    if (tid < 8)  sb3[tid] = make_float2(b3[2 * tid], b3[2 * tid + 1]);
    if (tid == 0) {
        // trainable RY angles; RZ gates provably cancel in the observable.
        float c[4], s[4];
#pragma unroll
        for (int i = 0; i < 4; i++) __sincosf(qw[2 * i], &s[i], &c[i]);
        float kv[30];
        kv[0]  =  c[0];                    kv[1]  = -s[0];
        kv[2]  =  c[0] * c[1];             kv[3]  = -c[0] * s[1];
        kv[4]  =  s[0] * c[1];             kv[5]  =  s[0] * s[1];
        kv[6]  =  c[0] * c[1] * c[2];      kv[7]  = -c[0] * c[1] * s[2];
        kv[8]  =  c[0] * s[1] * c[2];      kv[9]  =  c[0] * s[1] * s[2];
        kv[10] = -s[0] * c[1] * c[2];      kv[11] = -s[0] * c[1] * s[2];
        kv[12] = -s[0] * s[1] * c[2];      kv[13] = -s[0] * s[1] * s[2];
        kv[14] =  c[0] * c[1] * c[2] * c[3];   // Z1Z3
        kv[15] =  s[0] * c[1] * c[2] * c[3];   // Y0Y1Z3
        kv[16] = -c[0] * s[1] * c[2] * c[3];   // Z0X1X2Z3
        kv[17] =  c[0] * c[1] * s[2] * c[3];   // Z0Y2Y3
        kv[18] = -c[0] * c[1] * c[2] * s[3];   // Z0Z2X3
        kv[19] =  s[0] * s[1] * c[2] * c[3];   // X0X2Z3
        kv[20] = -s[0] * c[1] * s[2] * c[3];   // X0X1Y2Y3
        kv[21] =  s[0] * c[1] * c[2] * s[3];   // X0X1Z2X3
        kv[22] = -c[0] * s[1] * s[2] * c[3];   // Y1Z2Y3
        kv[23] = -c[0] * s[1] * c[2] * s[3];   // Y1Y2X3
        kv[24] =  c[0] * c[1] * s[2] * s[3];   // Z1X2
        kv[25] =  s[0] * s[1] * s[2] * c[3];   // Y0Z1Z2Y3
        kv[26] =  s[0] * s[1] * c[2] * s[3];   // Y0Z1Y2X3
        kv[27] =  s[0] * c[1] * s[2] * s[3];   // Y0Y1X2
        kv[28] = -c[0] * s[1] * s[2] * s[3];   // Z0X1
        kv[29] =  s[0] * s[1] * s[2] * s[3];   // X0
#pragma unroll
        for (int i = 0; i < 30; i++) sK[i] = make_float2(kv[i], kv[i]);
    }
    __syncthreads();

    const int r0 = blockIdx.x * (NT * 2) + tid;
    const int r1 = r0 + NT;
    if (r0 >= nrows) return;
    const bool has1 = (r1 < nrows);

    // ---- load the 8 used features for both rows ----
    const float4* xp0 = reinterpret_cast<const float4*>(x + (size_t)r0 * 16);
    const float4* xp1 = reinterpret_cast<const float4*>(x + (size_t)(has1 ? r1 : r0) * 16);
    float4 a0 = xp0[0], a1 = xp0[1];
    float4 c0 = xp1[0], c1 = xp1[1];
    float xsA[8] = {a0.x, a0.y, a0.z, a0.w, a1.x, a1.y, a1.z, a1.w};
    float xsB[8] = {c0.x, c0.y, c0.z, c0.w, c1.x, c1.y, c1.z, c1.w};

    // ---- per-qubit Bloch components, rows packed in lanes ----
    // X = sin(a)cos(b), Y = sin(a)sin(b), Z = cos(a);  a = pi*x[i], b = pi*x[i+4]
    P2 X[4], Y[4], Z[4];
#pragma unroll
    for (int i = 0; i < 4; i++) {
        float saA, caA, sbA, cbA, saB, caB, sbB, cbB;
        __sincosf(xsA[i]     * PI_F, &saA, &caA);
        __sincosf(xsA[i + 4] * PI_F, &sbA, &cbA);
        __sincosf(xsB[i]     * PI_F, &saB, &caB);
        __sincosf(xsB[i + 4] * PI_F, &sbB, &cbB);
        P2 sa = mk2(saA, saB), sb = mk2(sbA, sbB), cb = mk2(cbA, cbB);
        X[i] = mul2(sa, cb);
        Y[i] = mul2(sa, sb);
        Z[i] = mk2(caA, caB);
    }

    // ---- shared Pauli-product subexpressions ----
    P2 A  = mul2(X[0], X[1]);
    P2 B  = mul2(Y[0], Y[1]);
    P2 F  = mul2(X[1], X[2]);
    P2 H  = mul2(X[0], X[2]);
    P2 D  = mul2(X[2], X[3]);
    P2 E  = mul2(Y[2], Y[3]);
    P2 G  = mul2(Y[1], Y[2]);
    P2 ZF = mul2(Z[0], F);          // Z0 X1 X2
    P2 Z0Z2 = mul2(Z[0], Z[2]);
    P2 YZ   = mul2(Y[0], Z[1]);     // Y0 Z1
    P2 YZY  = mul2(YZ, Y[2]);       // Y0 Z1 Y2

#define KLD(n) ({ P2 _k; _k.f = sK[n]; _k; })

    // z0 = C0*Z0 - S0*X0X1
    P2 z0 = mul2(KLD(0), Z[0]);
    z0 = fma2(KLD(1), A, z0);

    // z1
    P2 z1 = mul2(KLD(2), Z[1]);
    z1 = fma2(KLD(3), ZF, z1);
    z1 = fma2(KLD(4), B, z1);
    z1 = fma2(KLD(5), H, z1);

    // z2
    P2 Z1D   = mul2(Z[1], D);           // Z1 X2 X3
    P2 X1X3  = mul2(X[1], X[3]);
    P2 ZX1X3 = mul2(Z[0], X1X3);        // Z0 X1 X3
    P2 AZ2   = mul2(A, Z[2]);           // X0 X1 Z2
    P2 BD    = mul2(B, D);              // Y0 Y1 X2 X3
    P2 X0X3  = mul2(X[0], X[3]);
    P2 z2 = mul2(KLD(6), Z0Z2);
    z2 = fma2(KLD(7),  Z1D,   z2);
    z2 = fma2(KLD(8),  G,     z2);
    z2 = fma2(KLD(9),  ZX1X3, z2);
    z2 = fma2(KLD(10), AZ2,   z2);
    z2 = fma2(KLD(11), BD,    z2);
    z2 = fma2(KLD(12), YZY,   z2);
    z2 = fma2(KLD(13), X0X3,  z2);

    // z3
    P2 Z1Z3 = mul2(Z[1], Z[3]);
    P2 BZ3  = mul2(B, Z[3]);
    P2 ZF3  = mul2(ZF, Z[3]);
    P2 Z0E  = mul2(Z[0], E);
    P2 ZZX  = mul2(Z0Z2, X[3]);
    P2 HZ3  = mul2(H, Z[3]);
    P2 AE   = mul2(A, E);
    P2 AZX  = mul2(AZ2, X[3]);
    P2 Y1Z2 = mul2(Y[1], Z[2]);
    P2 YZ2Y3 = mul2(Y1Z2, Y[3]);
    P2 GX3  = mul2(G, X[3]);
    P2 Z1X2 = mul2(Z[1], X[2]);
    P2 YZZ  = mul2(YZ, Z[2]);
    P2 YZZY = mul2(YZZ, Y[3]);
    P2 YZYX = mul2(YZY, X[3]);
    P2 BX2  = mul2(B, X[2]);
    P2 Z0X1 = mul2(Z[0], X[1]);
    P2 z3 = mul2(KLD(14), Z1Z3);
    z3 = fma2(KLD(15), BZ3,   z3);
    z3 = fma2(KLD(16), ZF3,   z3);
    z3 = fma2(KLD(17), Z0E,   z3);
    z3 = fma2(KLD(18), ZZX,   z3);
    z3 = fma2(KLD(19), HZ3,   z3);
    z3 = fma2(KLD(20), AE,    z3);
    z3 = fma2(KLD(21), AZX,   z3);
    z3 = fma2(KLD(22), YZ2Y3, z3);
    z3 = fma2(KLD(23), GX3,   z3);
    z3 = fma2(KLD(24), Z1X2,  z3);
    z3 = fma2(KLD(25), YZZY,  z3);
    z3 = fma2(KLD(26), YZYX,  z3);
    z3 = fma2(KLD(27), BX2,   z3);
    z3 = fma2(KLD(28), Z0X1,  z3);
    z3 = fma2(KLD(29), X[0],  z3);

    P2 zv[4] = {z0, z1, z2, z3};   // lanes = (rowA, rowB)

    // ================= MLP: neuron-pair packed =================
    P2 zdA[4], zdB[4];
#pragma unroll
    for (int k = 0; k < 4; k++) { zdA[k] = dup2(zv[k].f.x); zdB[k] = dup2(zv[k].f.y); }

    P2 h1pA[8], h1pB[8];
#pragma unroll
    for (int pp = 0; pp < 8; pp++) {
        const float4* wp = reinterpret_cast<const float4*>(sW1 + pp * 4);
        float4 w0 = wp[0], w1 = wp[1];
        P2 wk0 = mk2(w0.x, w0.y), wk1 = mk2(w0.z, w0.w);
        P2 wk2 = mk2(w1.x, w1.y), wk3 = mk2(w1.z, w1.w);
        P2 accA; accA.f = sb1[pp];
        P2 accB = accA;
        accA = fma2(wk0, zdA[0], accA); accB = fma2(wk0, zdB[0], accB);
        accA = fma2(wk1, zdA[1], accA); accB = fma2(wk1, zdB[1], accB);
        accA = fma2(wk2, zdA[2], accA); accB = fma2(wk2, zdB[2], accB);
        accA = fma2(wk3, zdA[3], accA); accB = fma2(wk3, zdB[3], accB);
        h1pA[pp] = relu2(accA); h1pB[pp] = relu2(accB);
    }

    P2 accA2[16], accB2[16];
#pragma unroll
    for (int pp = 0; pp < 16; pp++) { accA2[pp].f = sb2[pp]; accB2[pp] = accA2[pp]; }
#pragma unroll
    for (int ch = 0; ch < 2; ch++) {
        P2 hdA[8], hdB[8];
#pragma unroll
        for (int kk = 0; kk < 8; kk++) {
            int k = ch * 8 + kk;
            float vA = (k & 1) ? h1pA[k >> 1].f.y : h1pA[k >> 1].f.x;
            float vB = (k & 1) ? h1pB[k >> 1].f.y : h1pB[k >> 1].f.x;
            hdA[kk] = dup2(vA); hdB[kk] = dup2(vB);
        }
#pragma unroll
        for (int pp = 0; pp < 16; pp++) {
            const float4* wp = reinterpret_cast<const float4*>(sW2 + pp * 16 + ch * 8);
#pragma unroll
            for (int k4 = 0; k4 < 4; k4++) {
                float4 w = wp[k4];
                P2 wa = mk2(w.x, w.y), wb = mk2(w.z, w.w);
                accA2[pp] = fma2(wa, hdA[2 * k4],     accA2[pp]);
                accB2[pp] = fma2(wa, hdB[2 * k4],     accB2[pp]);
                accA2[pp] = fma2(wb, hdA[2 * k4 + 1], accA2[pp]);
                accB2[pp] = fma2(wb, hdB[2 * k4 + 1], accB2[pp]);
            }
        }
    }
#pragma unroll
    for (int pp = 0; pp < 16; pp++) { accA2[pp] = relu2(accA2[pp]); accB2[pp] = relu2(accB2[pp]); }

    P2 oA[8], oB[8];
#pragma unroll
    for (int pp = 0; pp < 8; pp++) { oA[pp].f = sb3[pp]; oB[pp] = oA[pp]; }
#pragma unroll
    for (int ch = 0; ch < 4; ch++) {
        P2 hdA[8], hdB[8];
#pragma unroll
        for (int kk = 0; kk < 8; kk++) {
            int k = ch * 8 + kk;
            float vA = (k & 1) ? accA2[k >> 1].f.y : accA2[k >> 1].f.x;
            float vB = (k & 1) ? accB2[k >> 1].f.y : accB2[k >> 1].f.x;
            hdA[kk] = dup2(vA); hdB[kk] = dup2(vB);
        }
#pragma unroll
        for (int pp = 0; pp < 8; pp++) {
            const float4* wp = reinterpret_cast<const float4*>(sW3 + pp * 32 + ch * 8);
#pragma unroll
            for (int k4 = 0; k4 < 4; k4++) {
                float4 w = wp[k4];
                P2 wa = mk2(w.x, w.y), wb = mk2(w.z, w.w);
                oA[pp] = fma2(wa, hdA[2 * k4],     oA[pp]);
                oB[pp] = fma2(wa, hdB[2 * k4],     oB[pp]);
                oA[pp] = fma2(wb, hdA[2 * k4 + 1], oA[pp]);
                oB[pp] = fma2(wb, hdB[2 * k4 + 1], oB[pp]);
            }
        }
    }

    float4* op0 = reinterpret_cast<float4*>(out + (size_t)r0 * 16);
#pragma unroll
    for (int q = 0; q < 4; q++)
        op0[q] = make_float4(oA[2 * q].f.x, oA[2 * q].f.y, oA[2 * q + 1].f.x, oA[2 * q + 1].f.y);
    if (has1) {
        float4* op1 = reinterpret_cast<float4*>(out + (size_t)r1 * 16);
#pragma unroll
        for (int q = 0; q < 4; q++)
            op1[q] = make_float4(oB[2 * q].f.x, oB[2 * q].f.y, oB[2 * q + 1].f.x, oB[2 * q + 1].f.y);
    }
}

extern "C" void kernel_launch(void* const* d_in, const int* in_sizes, int n_in,
                              void* d_out, int out_size) {
    const float* x  = (const float*)d_in[0];
    const float* qw = (const float*)d_in[1];
    const float* W1 = (const float*)d_in[2];
    const float* b1 = (const float*)d_in[3];
    const float* W2 = (const float*)d_in[4];
    const float* b2 = (const float*)d_in[5];
    const float* W3 = (const float*)d_in[6];
    const float* b3 = (const float*)d_in[7];
    float* out = (float*)d_out;

    int nrows = in_sizes[0] / 16;
    int grid = (nrows + NT * 2 - 1) / (NT * 2);
    qae4_kernel<<<grid, NT>>>(x, qw, W1, b1, W2, b2, W3, b3, out, nrows);
}